// round 5
// baseline (speedup 1.0000x reference)
#include <cuda_runtime.h>
#include <math.h>

// ---- problem constants ----
#define F      128
#define F3     384
#define NRBF   20
#define NQP    (NRBF / 2)     // q-pairs
#define NATOMS 8000
#define NEDGES 160000
#define NMOLS  100
#define NCONV  3
#define CUTOFF 5.0f

#define TA  8    // atoms per half in phi/upd kernels (16 per block)
#define TAM 4    // atoms per block in msg kernel
#define CAP 64   // max active edges per destination atom

// ---- device scratch ----
__device__ float g_s   [NATOMS * F];
__device__ float g_v   [NATOMS * F3];
__device__ float g_ds  [NATOMS * F];
__device__ float g_dv  [NATOMS * F3];
__device__ float g_phi [NATOMS * F3];
__device__ float g_rbf [NEDGES * NRBF];   // env-premultiplied
__device__ float g_env [NEDGES];
__device__ float g_unit[NEDGES * 3];
__device__ int   g_cnt [NATOMS];
__device__ int   g_list[NATOMS * CAP];

__device__ __forceinline__ float silu(float x) { return x / (1.0f + __expf(-x)); }

// packed fp32x2 helpers
#define FFMA2(acc, a, b) asm("fma.rn.f32x2 %0, %1, %2, %0;" : "+l"(acc) : "l"(a), "l"(b))
#define ADDX2(out, a, b) asm("add.rn.f32x2 %0, %1, %2;" : "=l"(out) : "l"(a), "l"(b))
__device__ __forceinline__ unsigned long long pk2(float x, float y) {
    unsigned long long r; asm("mov.b64 %0, {%1, %2};" : "=l"(r) : "f"(x), "f"(y)); return r;
}
__device__ __forceinline__ float2 upk2(unsigned long long v) {
    float2 o; asm("mov.b64 {%0, %1}, %2;" : "=f"(o.x), "=f"(o.y) : "l"(v)); return o;
}
// load 8 consecutive floats from 16B-aligned smem as 4 packed pairs (2x LDS.128)
__device__ __forceinline__ void lds_row8(const float* p, unsigned long long r[4]) {
    ulonglong2 a = *(const ulonglong2*)p;
    ulonglong2 b = *(const ulonglong2*)(p + 4);
    r[0] = a.x; r[1] = a.y; r[2] = b.x; r[3] = b.y;
}

// ---------------------------------------------------------------------------
// init
// ---------------------------------------------------------------------------
__global__ void k_init(const float* __restrict__ emb, const int* __restrict__ z)
{
    int a = blockIdx.x, f = threadIdx.x;
    g_s[a * F + f] = emb[z[a] * F + f];
    int b = a * F3 + f * 3;
    g_v[b] = 0.0f; g_v[b + 1] = 0.0f; g_v[b + 2] = 0.0f;
    if (f == 0) g_cnt[a] = 0;
}

// ---------------------------------------------------------------------------
// edge geometry + CSR build
// ---------------------------------------------------------------------------
__global__ void k_edges(const float* __restrict__ xyz, const int* __restrict__ nbrs, int E)
{
    int e = blockIdx.x * 256 + threadIdx.x;
    if (e >= E) return;
    int i = nbrs[2 * e], j = nbrs[2 * e + 1];
    float rx = xyz[3 * j]     - xyz[3 * i];
    float ry = xyz[3 * j + 1] - xyz[3 * i + 1];
    float rz = xyz[3 * j + 2] - xyz[3 * i + 2];
    float d  = sqrtf(rx * rx + ry * ry + rz * rz);
    float inv = 1.0f / d;
    float t = d * (1.0f / CUTOFF);
    if (d <= CUTOFF) {
        float env = 0.5f * (cospif(t) + 1.0f);
        g_env[e] = env;
        g_unit[3 * e]     = rx * inv;
        g_unit[3 * e + 1] = ry * inv;
        g_unit[3 * e + 2] = rz * inv;
        float s = env * inv;
        #pragma unroll
        for (int k = 0; k < NRBF; k++)
            g_rbf[e * NRBF + k] = sinpif((float)(k + 1) * t) * s;
        int pos = atomicAdd(&g_cnt[i], 1);
        if (pos < CAP) g_list[i * CAP + pos] = e;
    }
}

// ---------------------------------------------------------------------------
// phi = silu(s @ W1 + b1) @ W2 + b2   (256 threads = 2 halves, 16 atoms/block)
// ---------------------------------------------------------------------------
__global__ void __launch_bounds__(256)
k_phi(const float* __restrict__ W1, const float* __restrict__ B1,
      const float* __restrict__ W2, const float* __restrict__ B2)
{
    int tid  = threadIdx.x;
    int half = tid >> 7;
    int f    = tid & 127;
    int a0   = blockIdx.x * (2 * TA) + half * TA;

    __shared__ __align__(16) float ssT[2][F][TA];
    __shared__ __align__(16) float hhT[2][F][TA];

    #pragma unroll
    for (int t = 0; t < TA; t++) ssT[half][f][t] = g_s[(a0 + t) * F + f];
    __syncthreads();

    unsigned long long acc[TA / 2];
    {
        unsigned long long b = pk2(B1[f], B1[f]);
        #pragma unroll
        for (int p = 0; p < TA / 2; p++) acc[p] = b;
    }
    #pragma unroll 2
    for (int g = 0; g < F; g++) {
        float w = W1[g * F + f];
        unsigned long long ww = pk2(w, w);
        unsigned long long row[4];
        lds_row8(&ssT[half][g][0], row);
        #pragma unroll
        for (int p = 0; p < TA / 2; p++) FFMA2(acc[p], row[p], ww);
    }
    #pragma unroll
    for (int p = 0; p < TA / 2; p++) {
        float2 x = upk2(acc[p]);
        hhT[half][f][2 * p]     = silu(x.x);
        hhT[half][f][2 * p + 1] = silu(x.y);
    }
    __syncthreads();

    unsigned long long p0[TA / 2], p1[TA / 2], p2[TA / 2];
    {
        unsigned long long b0 = pk2(B2[f], B2[f]);
        unsigned long long b1 = pk2(B2[F + f], B2[F + f]);
        unsigned long long b2 = pk2(B2[2 * F + f], B2[2 * F + f]);
        #pragma unroll
        for (int p = 0; p < TA / 2; p++) { p0[p] = b0; p1[p] = b1; p2[p] = b2; }
    }
    #pragma unroll 2
    for (int g = 0; g < F; g++) {
        const float* w = W2 + g * F3;
        unsigned long long w0 = pk2(w[f], w[f]);
        unsigned long long w1 = pk2(w[F + f], w[F + f]);
        unsigned long long w2 = pk2(w[2 * F + f], w[2 * F + f]);
        unsigned long long row[4];
        lds_row8(&hhT[half][g][0], row);
        #pragma unroll
        for (int p = 0; p < TA / 2; p++) {
            FFMA2(p0[p], row[p], w0);
            FFMA2(p1[p], row[p], w1);
            FFMA2(p2[p], row[p], w2);
        }
    }
    #pragma unroll
    for (int p = 0; p < TA / 2; p++) {
        float2 x0 = upk2(p0[p]), x1 = upk2(p1[p]), x2 = upk2(p2[p]);
        int a = a0 + 2 * p;
        g_phi[a * F3 + f]               = x0.x;
        g_phi[(a + 1) * F3 + f]         = x0.y;
        g_phi[a * F3 + F + f]           = x1.x;
        g_phi[(a + 1) * F3 + F + f]     = x1.y;
        g_phi[a * F3 + 2 * F + f]       = x2.x;
        g_phi[(a + 1) * F3 + 2 * F + f] = x2.y;
    }
}

// ---------------------------------------------------------------------------
// message pass over CSR buckets.
// q-pair packing: rbf pairs come straight from smem (no lane-dup MOVs);
// ch0/ch1 q-pair weights in regs, ch2 q-pair weights in smem.
// 6 independent FFMA2 chains of depth 5 per edge.  phi/v gathers prefetched.
// ---------------------------------------------------------------------------
__global__ void __launch_bounds__(128)
k_msg(const float* __restrict__ RW, const float* __restrict__ RB,
      const int* __restrict__ nbrs)
{
    __shared__ unsigned long long rw2p[NQP * F];   // ch2 weight q-pairs, 10 KB
    __shared__ int   sj  [CAP];
    __shared__ float senv[CAP];
    __shared__ float sux [CAP];
    __shared__ float suy [CAP];
    __shared__ float suz [CAP];
    __shared__ __align__(16) unsigned long long srbf[CAP][NQP];  // rbf q-pairs, 5 KB

    int f = threadIdx.x;

    // ch0/ch1 q-pair weights -> registers
    unsigned long long w0p[NQP], w1p[NQP];
    #pragma unroll
    for (int p = 0; p < NQP; p++) {
        w0p[p] = pk2(RW[(2 * p) * F3 + f],     RW[(2 * p + 1) * F3 + f]);
        w1p[p] = pk2(RW[(2 * p) * F3 + F + f], RW[(2 * p + 1) * F3 + F + f]);
    }
    // ch2 q-pair weights -> smem
    for (int idx = f; idx < NQP * F; idx += 128) {
        int p = idx >> 7, ff = idx & 127;
        rw2p[idx] = pk2(RW[(2 * p) * F3 + 2 * F + ff], RW[(2 * p + 1) * F3 + 2 * F + ff]);
    }
    float rb0 = RB[f], rb1 = RB[F + f], rb2 = RB[2 * F + f];

    int abase = blockIdx.x * TAM;

    for (int it = 0; it < TAM; it++) {
        int a = abase + it;
        int n = g_cnt[a];
        if (n > CAP) n = CAP;

        __syncthreads();   // prev iter smem reads done; also covers rw2p fill
        if (f < n) {
            int e = g_list[a * CAP + f];
            sj  [f] = nbrs[2 * e + 1];
            senv[f] = g_env[e];
            sux [f] = g_unit[3 * e];
            suy [f] = g_unit[3 * e + 1];
            suz [f] = g_unit[3 * e + 2];
            const float4* rp = (const float4*)(g_rbf + e * NRBF);
            float4* dst = (float4*)&srbf[f][0];
            #pragma unroll
            for (int x = 0; x < NRBF / 4; x++) dst[x] = rp[x];
        }
        __syncthreads();

        float ds = 0.0f, dv0 = 0.0f, dv1 = 0.0f, dv2 = 0.0f;
        float pj0 = 0.f, pj1 = 0.f, pj2 = 0.f, vj0 = 0.f, vj1 = 0.f, vj2 = 0.f;
        if (n > 0) {
            int j = sj[0];
            const float* pj = g_phi + j * F3;
            pj0 = pj[f]; pj1 = pj[F + f]; pj2 = pj[2 * F + f];
            const float* vj = g_v + j * F3 + f * 3;
            vj0 = vj[0]; vj1 = vj[1]; vj2 = vj[2];
        }
        for (int k = 0; k < n; k++) {
            float npj0 = 0.f, npj1 = 0.f, npj2 = 0.f, nvj0 = 0.f, nvj1 = 0.f, nvj2 = 0.f;
            if (k + 1 < n) {
                int jn = sj[k + 1];
                const float* pj = g_phi + jn * F3;
                npj0 = pj[f]; npj1 = pj[F + f]; npj2 = pj[2 * F + f];
                const float* vj = g_v + jn * F3 + f * 3;
                nvj0 = vj[0]; nvj1 = vj[1]; nvj2 = vj[2];
            }

            // 6 independent chains (3 channels x even/odd pair)
            unsigned long long c0a = 0ULL, c0b = 0ULL;
            unsigned long long c1a = 0ULL, c1b = 0ULL;
            unsigned long long c2a = 0ULL, c2b = 0ULL;
            const ulonglong2* rp2 = (const ulonglong2*)&srbf[k][0];
            #pragma unroll
            for (int p = 0; p < NQP; p += 2) {
                ulonglong2 rr = rp2[p >> 1];
                FFMA2(c0a, rr.x, w0p[p]);     FFMA2(c0b, rr.y, w0p[p + 1]);
                FFMA2(c1a, rr.x, w1p[p]);     FFMA2(c1b, rr.y, w1p[p + 1]);
                FFMA2(c2a, rr.x, rw2p[p * F + f]);
                FFMA2(c2b, rr.y, rw2p[(p + 1) * F + f]);
            }
            unsigned long long t0, t1, t2;
            ADDX2(t0, c0a, c0b); ADDX2(t1, c1a, c1b); ADDX2(t2, c2a, c2b);
            float2 x0 = upk2(t0), x1 = upk2(t1), x2 = upk2(t2);
            float env = senv[k];
            float w0v = x0.x + x0.y + env * rb0;
            float w1v = x1.x + x1.y + env * rb1;
            float w2v = x2.x + x2.y + env * rb2;

            float sp0 = pj0 * w0v;
            float sp1 = pj1 * w1v;
            float sp2 = pj2 * w2v;
            ds += sp1;
            dv0 += sp2 * sux[k] + sp0 * vj0;
            dv1 += sp2 * suy[k] + sp0 * vj1;
            dv2 += sp2 * suz[k] + sp0 * vj2;

            pj0 = npj0; pj1 = npj1; pj2 = npj2;
            vj0 = nvj0; vj1 = nvj1; vj2 = nvj2;
        }
        g_ds[a * F + f] = ds;
        g_dv[a * F3 + f * 3]     = dv0;
        g_dv[a * F3 + f * 3 + 1] = dv1;
        g_dv[a * F3 + f * 3 + 2] = dv2;
    }
}

// ---------------------------------------------------------------------------
// update block (256 threads = 2 halves x 8 atoms)
// ---------------------------------------------------------------------------
__global__ void __launch_bounds__(256)
k_upd(const float* __restrict__ U,  const float* __restrict__ V,
      const float* __restrict__ W1, const float* __restrict__ B1,
      const float* __restrict__ W2, const float* __restrict__ B2)
{
    int tid  = threadIdx.x;
    int half = tid >> 7;
    int f    = tid & 127;
    int a0   = blockIdx.x * (2 * TA) + half * TA;

    __shared__ __align__(16) float svT[2][F][3][TA];    // 24 KB
    __shared__ __align__(16) float stT[2][2 * F][TA];   // 16 KB (reused as shT)
    float (*shT)[F][TA] = (float (*)[F][TA])&stT[0][0][0];

    float snew[TA];
    #pragma unroll
    for (int t = 0; t < TA; t++) {
        int a = a0 + t;
        float s1 = g_s[a * F + f] + g_ds[a * F + f];
        snew[t]         = s1;
        stT[half][f][t] = s1;
        #pragma unroll
        for (int d = 0; d < 3; d++)
            svT[half][f][d][t] = g_v[a * F3 + f * 3 + d] + g_dv[a * F3 + f * 3 + d];
    }
    __syncthreads();

    unsigned long long ua[3][TA / 2], wa[3][TA / 2];
    #pragma unroll
    for (int d = 0; d < 3; d++)
        #pragma unroll
        for (int p = 0; p < TA / 2; p++) { ua[d][p] = 0ULL; wa[d][p] = 0ULL; }
    #pragma unroll 2
    for (int g = 0; g < F; g++) {
        float Ug = U[g * F + f], Vg = V[g * F + f];
        unsigned long long Up = pk2(Ug, Ug), Vp = pk2(Vg, Vg);
        #pragma unroll
        for (int d = 0; d < 3; d++) {
            unsigned long long row[4];
            lds_row8(&svT[half][g][d][0], row);
            #pragma unroll
            for (int p = 0; p < TA / 2; p++) {
                FFMA2(ua[d][p], row[p], Up);
                FFMA2(wa[d][p], row[p], Vp);
            }
        }
    }
    float u[TA][3], uw[TA];
    #pragma unroll
    for (int p = 0; p < TA / 2; p++) {
        float wv[2][3];
        #pragma unroll
        for (int d = 0; d < 3; d++) {
            float2 xu = upk2(ua[d][p]);
            float2 xw = upk2(wa[d][p]);
            u[2 * p][d] = xu.x; u[2 * p + 1][d] = xu.y;
            wv[0][d] = xw.x;    wv[1][d] = xw.y;
        }
        #pragma unroll
        for (int h = 0; h < 2; h++) {
            int t = 2 * p + h;
            float n2 = wv[h][0] * wv[h][0] + wv[h][1] * wv[h][1] + wv[h][2] * wv[h][2];
            stT[half][F + f][t] = sqrtf(n2 + 1e-15f);
            uw[t] = u[t][0] * wv[h][0] + u[t][1] * wv[h][1] + u[t][2] * wv[h][2];
        }
    }
    __syncthreads();

    unsigned long long hacc[TA / 2];
    {
        unsigned long long b = pk2(B1[f], B1[f]);
        #pragma unroll
        for (int p = 0; p < TA / 2; p++) hacc[p] = b;
    }
    #pragma unroll 2
    for (int r = 0; r < 2 * F; r++) {
        float wv = W1[r * F + f];
        unsigned long long ww = pk2(wv, wv);
        unsigned long long row[4];
        lds_row8(&stT[half][r][0], row);
        #pragma unroll
        for (int p = 0; p < TA / 2; p++) FFMA2(hacc[p], row[p], ww);
    }
    __syncthreads();
    #pragma unroll
    for (int p = 0; p < TA / 2; p++) {
        float2 x = upk2(hacc[p]);
        shT[half][f][2 * p]     = silu(x.x);
        shT[half][f][2 * p + 1] = silu(x.y);
    }
    __syncthreads();

    unsigned long long p0[TA / 2], p1[TA / 2], p2[TA / 2];
    {
        unsigned long long b0 = pk2(B2[f], B2[f]);
        unsigned long long b1 = pk2(B2[F + f], B2[F + f]);
        unsigned long long b2 = pk2(B2[2 * F + f], B2[2 * F + f]);
        #pragma unroll
        for (int p = 0; p < TA / 2; p++) { p0[p] = b0; p1[p] = b1; p2[p] = b2; }
    }
    #pragma unroll 2
    for (int g = 0; g < F; g++) {
        const float* wr = W2 + g * F3;
        unsigned long long w0 = pk2(wr[f], wr[f]);
        unsigned long long w1 = pk2(wr[F + f], wr[F + f]);
        unsigned long long w2 = pk2(wr[2 * F + f], wr[2 * F + f]);
        unsigned long long row[4];
        lds_row8(&shT[half][g][0], row);
        #pragma unroll
        for (int p = 0; p < TA / 2; p++) {
            FFMA2(p0[p], row[p], w0);
            FFMA2(p1[p], row[p], w1);
            FFMA2(p2[p], row[p], w2);
        }
    }
    #pragma unroll
    for (int p = 0; p < TA / 2; p++) {
        float2 avv = upk2(p0[p]), asv = upk2(p1[p]), ass = upk2(p2[p]);
        #pragma unroll
        for (int h = 0; h < 2; h++) {
            int t = 2 * p + h;
            int a = a0 + t;
            float a_vv = h ? avv.y : avv.x;
            float a_sv = h ? asv.y : asv.x;
            float a_ss = h ? ass.y : ass.x;
            g_s[a * F + f] = snew[t] + uw[t] * a_sv + a_ss;
            #pragma unroll
            for (int d = 0; d < 3; d++)
                g_v[a * F3 + f * 3 + d] = svT[half][f][d][t] + u[t][d] * a_vv;
        }
    }
}

// ---------------------------------------------------------------------------
// readout: 16 atoms per block
// ---------------------------------------------------------------------------
#define TR 16

__global__ void k_zero_out(float* out)
{
    int t = threadIdx.x;
    if (t < NMOLS) out[t] = 0.0f;
}

__global__ void __launch_bounds__(128)
k_readout(const float* __restrict__ W1, const float* __restrict__ B1,
          const float* __restrict__ W2, const float* __restrict__ B2,
          const int* __restrict__ mol, float* __restrict__ out)
{
    int tid  = threadIdx.x;
    int half = tid >> 6;
    int t    = tid & 63;
    int ab   = blockIdx.x * TR;

    __shared__ __align__(16) float ssT[F][TR];
    __shared__ float red[TR][64];

    for (int x = tid; x < TR * F; x += 128) {
        int aa = x >> 7, ff = x & 127;
        ssT[ff][aa] = g_s[(ab + aa) * F + ff];
    }
    __syncthreads();

    unsigned long long acc[4];
    {
        unsigned long long b = pk2(B1[t], B1[t]);
        #pragma unroll
        for (int p = 0; p < 4; p++) acc[p] = b;
    }
    for (int g = 0; g < F; g++) {
        float w = W1[g * 64 + t];
        unsigned long long ww = pk2(w, w);
        unsigned long long row[4];
        lds_row8(&ssT[g][half * 8], row);
        #pragma unroll
        for (int p = 0; p < 4; p++) FFMA2(acc[p], row[p], ww);
    }
    float w2v = W2[t];
    #pragma unroll
    for (int p = 0; p < 4; p++) {
        float2 x = upk2(acc[p]);
        red[half * 8 + 2 * p][t]     = silu(x.x) * w2v;
        red[half * 8 + 2 * p + 1][t] = silu(x.y) * w2v;
    }
    __syncthreads();

    if (tid < TR) {
        float e = B2[0];
        #pragma unroll
        for (int q = 0; q < 64; q++) e += red[tid][q];
        atomicAdd(&out[mol[ab + tid]], e);
    }
}

// ---------------------------------------------------------------------------
// launch
// ---------------------------------------------------------------------------
extern "C" void kernel_launch(void* const* d_in, const int* in_sizes, int n_in,
                              void* d_out, int out_size)
{
    const float* xyz    = (const float*)d_in[0];
    const float* emb    = (const float*)d_in[1];
    const float* msg_w1 = (const float*)d_in[2];
    const float* msg_b1 = (const float*)d_in[3];
    const float* msg_w2 = (const float*)d_in[4];
    const float* msg_b2 = (const float*)d_in[5];
    const float* rbf_w  = (const float*)d_in[6];
    const float* rbf_b  = (const float*)d_in[7];
    const float* upd_u  = (const float*)d_in[8];
    const float* upd_v  = (const float*)d_in[9];
    const float* upd_w1 = (const float*)d_in[10];
    const float* upd_b1 = (const float*)d_in[11];
    const float* upd_w2 = (const float*)d_in[12];
    const float* upd_b2 = (const float*)d_in[13];
    const float* ro_w1  = (const float*)d_in[14];
    const float* ro_b1  = (const float*)d_in[15];
    const float* ro_w2  = (const float*)d_in[16];
    const float* ro_b2  = (const float*)d_in[17];
    const int*   z      = (const int*)d_in[18];
    const int*   nbrs   = (const int*)d_in[19];
    const int*   mol    = (const int*)d_in[20];
    float*       out    = (float*)d_out;

    int E = in_sizes[19] / 2;

    k_init <<<NATOMS, 128>>>(emb, z);
    k_edges<<<(E + 255) / 256, 256>>>(xyz, nbrs, E);

    for (int c = 0; c < NCONV; c++) {
        k_phi<<<NATOMS / (2 * TA), 256>>>(msg_w1 + c * F * F,     msg_b1 + c * F,
                                          msg_w2 + c * F * F3,    msg_b2 + c * F3);
        k_msg<<<NATOMS / TAM, 128>>>(rbf_w + c * NRBF * F3, rbf_b + c * F3, nbrs);
        k_upd<<<NATOMS / (2 * TA), 256>>>(upd_u  + c * F * F,     upd_v  + c * F * F,
                                          upd_w1 + c * 2 * F * F, upd_b1 + c * F,
                                          upd_w2 + c * F * F3,    upd_b2 + c * F3);
    }

    k_zero_out<<<1, 128>>>(out);
    k_readout <<<NATOMS / TR, 128>>>(ro_w1, ro_b1, ro_w2, ro_b2, mol, out);
}

// round 6
// speedup vs baseline: 1.3303x; 1.3303x over previous
#include <cuda_runtime.h>
#include <math.h>

// ---- problem constants ----
#define F      128
#define F3     384
#define NRBF   20
#define NATOMS 8000
#define NEDGES 160000
#define NMOLS  100
#define NCONV  3
#define CUTOFF 5.0f

#define TA  8    // atoms per half in phi/upd kernels (16 per block)
#define TAM 2    // atoms per block in msg kernel
#define CAP 64   // max active edges per destination atom
#define EW  16   // edges per block in k_ws

// ---- device scratch ----
__device__ float g_s    [NATOMS * F];
__device__ float g_v    [NATOMS * F3];
__device__ float g_ds   [NATOMS * F];
__device__ float g_dv   [NATOMS * F3];
__device__ float g_phi  [NATOMS * F3];
__device__ float g_ws   [NEDGES * F3];    // per-edge filter weights (compact idx)
__device__ float g_rbfc [NEDGES * NRBF];  // env-premultiplied rbf (compact)
__device__ float g_envc [NEDGES];         // envelope (compact)
__device__ float g_unitc[NEDGES * 3];     // unit vectors (compact)
__device__ int   g_aj   [NEDGES];         // source atom j (compact)
__device__ int   g_nact;                  // number of active edges
__device__ int   g_cnt  [NATOMS];
__device__ int   g_list [NATOMS * CAP];   // compact edge indices per dest atom

__device__ __forceinline__ float silu(float x) { return x / (1.0f + __expf(-x)); }

// packed fp32x2 helpers
#define FFMA2(acc, a, b) asm("fma.rn.f32x2 %0, %1, %2, %0;" : "+l"(acc) : "l"(a), "l"(b))
#define ADDX2(out, a, b) asm("add.rn.f32x2 %0, %1, %2;" : "=l"(out) : "l"(a), "l"(b))
__device__ __forceinline__ unsigned long long pk2(float x, float y) {
    unsigned long long r; asm("mov.b64 %0, {%1, %2};" : "=l"(r) : "f"(x), "f"(y)); return r;
}
__device__ __forceinline__ float2 upk2(unsigned long long v) {
    float2 o; asm("mov.b64 {%0, %1}, %2;" : "=f"(o.x), "=f"(o.y) : "l"(v)); return o;
}

// ---------------------------------------------------------------------------
// init
// ---------------------------------------------------------------------------
__global__ void k_init(const float* __restrict__ emb, const int* __restrict__ z)
{
    int a = blockIdx.x, f = threadIdx.x;
    g_s[a * F + f] = emb[z[a] * F + f];
    int b = a * F3 + f * 3;
    g_v[b] = 0.0f; g_v[b + 1] = 0.0f; g_v[b + 2] = 0.0f;
    if (f == 0) g_cnt[a] = 0;
    if (f == 0 && a == 0) g_nact = 0;
}

// ---------------------------------------------------------------------------
// edge geometry + compaction + per-destination CSR build
// ---------------------------------------------------------------------------
__global__ void k_edges(const float* __restrict__ xyz, const int* __restrict__ nbrs, int E)
{
    int e = blockIdx.x * 256 + threadIdx.x;
    if (e >= E) return;
    int i = nbrs[2 * e], j = nbrs[2 * e + 1];
    float rx = xyz[3 * j]     - xyz[3 * i];
    float ry = xyz[3 * j + 1] - xyz[3 * i + 1];
    float rz = xyz[3 * j + 2] - xyz[3 * i + 2];
    float d  = sqrtf(rx * rx + ry * ry + rz * rz);
    float inv = 1.0f / d;
    float t = d * (1.0f / CUTOFF);
    if (d <= CUTOFF) {
        float env = 0.5f * (cospif(t) + 1.0f);
        int c = atomicAdd(&g_nact, 1);
        g_aj  [c] = j;
        g_envc[c] = env;
        g_unitc[3 * c]     = rx * inv;
        g_unitc[3 * c + 1] = ry * inv;
        g_unitc[3 * c + 2] = rz * inv;
        float s = env * inv;
        #pragma unroll
        for (int k = 0; k < NRBF; k++)
            g_rbfc[c * NRBF + k] = sinpif((float)(k + 1) * t) * s;
        int slot = atomicAdd(&g_cnt[i], 1);
        if (slot < CAP) g_list[i * CAP + slot] = c;
    }
}

// ---------------------------------------------------------------------------
// phi = silu(s @ W1 + b1) @ W2 + b2   (256 threads = 2 halves, 16 atoms/block)
// ---------------------------------------------------------------------------
__global__ void __launch_bounds__(256)
k_phi(const float* __restrict__ W1, const float* __restrict__ B1,
      const float* __restrict__ W2, const float* __restrict__ B2)
{
    int tid  = threadIdx.x;
    int half = tid >> 7;
    int f    = tid & 127;
    int a0   = blockIdx.x * (2 * TA) + half * TA;

    __shared__ float ssT[2][F][TA];
    __shared__ float hhT[2][F][TA];

    #pragma unroll
    for (int t = 0; t < TA; t++) ssT[half][f][t] = g_s[(a0 + t) * F + f];
    __syncthreads();

    unsigned long long acc[TA / 2];
    {
        unsigned long long b = pk2(B1[f], B1[f]);
        #pragma unroll
        for (int p = 0; p < TA / 2; p++) acc[p] = b;
    }
    for (int g = 0; g < F; g++) {
        float w = W1[g * F + f];
        unsigned long long ww = pk2(w, w);
        const unsigned long long* row = (const unsigned long long*)&ssT[half][g][0];
        #pragma unroll
        for (int p = 0; p < TA / 2; p++) FFMA2(acc[p], row[p], ww);
    }
    #pragma unroll
    for (int p = 0; p < TA / 2; p++) {
        float2 x = upk2(acc[p]);
        hhT[half][f][2 * p]     = silu(x.x);
        hhT[half][f][2 * p + 1] = silu(x.y);
    }
    __syncthreads();

    unsigned long long p0[TA / 2], p1[TA / 2], p2[TA / 2];
    {
        unsigned long long b0 = pk2(B2[f], B2[f]);
        unsigned long long b1 = pk2(B2[F + f], B2[F + f]);
        unsigned long long b2 = pk2(B2[2 * F + f], B2[2 * F + f]);
        #pragma unroll
        for (int p = 0; p < TA / 2; p++) { p0[p] = b0; p1[p] = b1; p2[p] = b2; }
    }
    for (int g = 0; g < F; g++) {
        const float* w = W2 + g * F3;
        unsigned long long w0 = pk2(w[f], w[f]);
        unsigned long long w1 = pk2(w[F + f], w[F + f]);
        unsigned long long w2 = pk2(w[2 * F + f], w[2 * F + f]);
        const unsigned long long* row = (const unsigned long long*)&hhT[half][g][0];
        #pragma unroll
        for (int p = 0; p < TA / 2; p++) {
            FFMA2(p0[p], row[p], w0);
            FFMA2(p1[p], row[p], w1);
            FFMA2(p2[p], row[p], w2);
        }
    }
    #pragma unroll
    for (int p = 0; p < TA / 2; p++) {
        float2 x0 = upk2(p0[p]), x1 = upk2(p1[p]), x2 = upk2(p2[p]);
        int a = a0 + 2 * p;
        g_phi[a * F3 + f]               = x0.x;
        g_phi[(a + 1) * F3 + f]         = x0.y;
        g_phi[a * F3 + F + f]           = x1.x;
        g_phi[(a + 1) * F3 + F + f]     = x1.y;
        g_phi[a * F3 + 2 * F + f]       = x2.x;
        g_phi[(a + 1) * F3 + 2 * F + f] = x2.y;
    }
}

// ---------------------------------------------------------------------------
// k_ws: edge-parallel w_s = env*(rbf @ RW + RB) for compact active edges.
// ch0/ch1 weights in regs (packed), ch2 in smem.  EW edges per block.
// ---------------------------------------------------------------------------
__global__ void __launch_bounds__(128)
k_ws(const float* __restrict__ RW, const float* __restrict__ RB)
{
    int f    = threadIdx.x;
    int nact = g_nact;
    int base = blockIdx.x * EW;
    if (base >= nact) return;

    unsigned long long rw01[NRBF];
    #pragma unroll
    for (int q = 0; q < NRBF; q++)
        rw01[q] = pk2(RW[q * F3 + f], RW[q * F3 + F + f]);
    __shared__ float rw2s[NRBF * F];
    for (int idx = f; idx < NRBF * F; idx += 128) {
        int q = idx >> 7, ff = idx & 127;
        rw2s[idx] = RW[q * F3 + 2 * F + ff];
    }
    float rb0 = RB[f], rb1 = RB[F + f], rb2 = RB[2 * F + f];

    __shared__ float srbf[EW][NRBF];
    __shared__ float senv[EW];
    int m = nact - base; if (m > EW) m = EW;
    for (int x = f; x < m * NRBF; x += 128)
        srbf[x / NRBF][x % NRBF] = g_rbfc[base * NRBF + x];
    if (f < m) senv[f] = g_envc[base + f];
    __syncthreads();

    for (int k = 0; k < m; k++) {
        float env = senv[k];
        unsigned long long wA = pk2(env * rb0, env * rb1);
        unsigned long long wB = pk2(0.0f, 0.0f);
        float w2a = env * rb2, w2b = 0.0f;
        #pragma unroll
        for (int q = 0; q < NRBF; q += 2) {
            float r0 = srbf[k][q];
            float r1 = srbf[k][q + 1];
            FFMA2(wA, pk2(r0, r0), rw01[q]);
            FFMA2(wB, pk2(r1, r1), rw01[q + 1]);
            w2a = fmaf(r0, rw2s[q * F + f], w2a);
            w2b = fmaf(r1, rw2s[(q + 1) * F + f], w2b);
        }
        unsigned long long wT; ADDX2(wT, wA, wB);
        float2 xy = upk2(wT);
        int c = base + k;
        g_ws[c * F3 + f]         = xy.x;
        g_ws[c * F3 + F + f]     = xy.y;
        g_ws[c * F3 + 2 * F + f] = w2a + w2b;
    }
}

// ---------------------------------------------------------------------------
// lean message pass: per destination atom, gather w_s/phi/v with one-edge-
// ahead prefetch; no weights in registers, short dependence chains.
// ---------------------------------------------------------------------------
__global__ void __launch_bounds__(128)
k_msg(void)
{
    __shared__ int   sc [CAP];
    __shared__ int   sj [CAP];
    __shared__ float sux[CAP];
    __shared__ float suy[CAP];
    __shared__ float suz[CAP];

    int f = threadIdx.x;
    int abase = blockIdx.x * TAM;

    for (int it = 0; it < TAM; it++) {
        int a = abase + it;
        int n = g_cnt[a];
        if (n > CAP) n = CAP;

        __syncthreads();
        if (f < n) {
            int c = g_list[a * CAP + f];
            sc[f] = c;
            sj[f] = g_aj[c];
            sux[f] = g_unitc[3 * c];
            suy[f] = g_unitc[3 * c + 1];
            suz[f] = g_unitc[3 * c + 2];
        }
        __syncthreads();

        float ds = 0.0f, dv0 = 0.0f, dv1 = 0.0f, dv2 = 0.0f;
        float w0 = 0.f, w1 = 0.f, w2 = 0.f;
        float pj0 = 0.f, pj1 = 0.f, pj2 = 0.f, vj0 = 0.f, vj1 = 0.f, vj2 = 0.f;
        if (n > 0) {
            int c = sc[0], j = sj[0];
            const float* wp = g_ws + c * F3;
            w0 = wp[f]; w1 = wp[F + f]; w2 = wp[2 * F + f];
            const float* pj = g_phi + j * F3;
            pj0 = pj[f]; pj1 = pj[F + f]; pj2 = pj[2 * F + f];
            const float* vj = g_v + j * F3 + f * 3;
            vj0 = vj[0]; vj1 = vj[1]; vj2 = vj[2];
        }
        for (int k = 0; k < n; k++) {
            float nw0 = 0.f, nw1 = 0.f, nw2 = 0.f;
            float npj0 = 0.f, npj1 = 0.f, npj2 = 0.f, nvj0 = 0.f, nvj1 = 0.f, nvj2 = 0.f;
            if (k + 1 < n) {
                int c = sc[k + 1], j = sj[k + 1];
                const float* wp = g_ws + c * F3;
                nw0 = wp[f]; nw1 = wp[F + f]; nw2 = wp[2 * F + f];
                const float* pj = g_phi + j * F3;
                npj0 = pj[f]; npj1 = pj[F + f]; npj2 = pj[2 * F + f];
                const float* vj = g_v + j * F3 + f * 3;
                nvj0 = vj[0]; nvj1 = vj[1]; nvj2 = vj[2];
            }
            float sp0 = pj0 * w0;
            float sp1 = pj1 * w1;
            float sp2 = pj2 * w2;
            ds  += sp1;
            dv0 += sp2 * sux[k] + sp0 * vj0;
            dv1 += sp2 * suy[k] + sp0 * vj1;
            dv2 += sp2 * suz[k] + sp0 * vj2;
            w0 = nw0; w1 = nw1; w2 = nw2;
            pj0 = npj0; pj1 = npj1; pj2 = npj2;
            vj0 = nvj0; vj1 = nvj1; vj2 = nvj2;
        }
        g_ds[a * F + f] = ds;
        g_dv[a * F3 + f * 3]     = dv0;
        g_dv[a * F3 + f * 3 + 1] = dv1;
        g_dv[a * F3 + f * 3 + 2] = dv2;
    }
}

// ---------------------------------------------------------------------------
// update block (256 threads = 2 halves x 8 atoms)
// ---------------------------------------------------------------------------
__global__ void __launch_bounds__(256)
k_upd(const float* __restrict__ U,  const float* __restrict__ V,
      const float* __restrict__ W1, const float* __restrict__ B1,
      const float* __restrict__ W2, const float* __restrict__ B2)
{
    int tid  = threadIdx.x;
    int half = tid >> 7;
    int f    = tid & 127;
    int a0   = blockIdx.x * (2 * TA) + half * TA;

    __shared__ float svT[2][F][3][TA];    // 24 KB
    __shared__ float stT[2][2 * F][TA];   // 16 KB (reused as shT after W1 pass)
    float (*shT)[F][TA] = (float (*)[F][TA])&stT[0][0][0];

    float snew[TA];
    #pragma unroll
    for (int t = 0; t < TA; t++) {
        int a = a0 + t;
        float s1 = g_s[a * F + f] + g_ds[a * F + f];
        snew[t]         = s1;
        stT[half][f][t] = s1;
        #pragma unroll
        for (int d = 0; d < 3; d++)
            svT[half][f][d][t] = g_v[a * F3 + f * 3 + d] + g_dv[a * F3 + f * 3 + d];
    }
    __syncthreads();

    unsigned long long ua[3][TA / 2], wa[3][TA / 2];
    #pragma unroll
    for (int d = 0; d < 3; d++)
        #pragma unroll
        for (int p = 0; p < TA / 2; p++) { ua[d][p] = 0ULL; wa[d][p] = 0ULL; }
    for (int g = 0; g < F; g++) {
        float Ug = U[g * F + f], Vg = V[g * F + f];
        unsigned long long Up = pk2(Ug, Ug), Vp = pk2(Vg, Vg);
        #pragma unroll
        for (int d = 0; d < 3; d++) {
            const unsigned long long* row = (const unsigned long long*)&svT[half][g][d][0];
            #pragma unroll
            for (int p = 0; p < TA / 2; p++) {
                unsigned long long r = row[p];
                FFMA2(ua[d][p], r, Up);
                FFMA2(wa[d][p], r, Vp);
            }
        }
    }
    float u[TA][3], uw[TA];
    #pragma unroll
    for (int p = 0; p < TA / 2; p++) {
        float wv[2][3];
        #pragma unroll
        for (int d = 0; d < 3; d++) {
            float2 xu = upk2(ua[d][p]);
            float2 xw = upk2(wa[d][p]);
            u[2 * p][d] = xu.x; u[2 * p + 1][d] = xu.y;
            wv[0][d] = xw.x;    wv[1][d] = xw.y;
        }
        #pragma unroll
        for (int h = 0; h < 2; h++) {
            int t = 2 * p + h;
            float n2 = wv[h][0] * wv[h][0] + wv[h][1] * wv[h][1] + wv[h][2] * wv[h][2];
            stT[half][F + f][t] = sqrtf(n2 + 1e-15f);
            uw[t] = u[t][0] * wv[h][0] + u[t][1] * wv[h][1] + u[t][2] * wv[h][2];
        }
    }
    __syncthreads();

    unsigned long long hacc[TA / 2];
    {
        unsigned long long b = pk2(B1[f], B1[f]);
        #pragma unroll
        for (int p = 0; p < TA / 2; p++) hacc[p] = b;
    }
    for (int r = 0; r < 2 * F; r++) {
        float wv = W1[r * F + f];
        unsigned long long ww = pk2(wv, wv);
        const unsigned long long* row = (const unsigned long long*)&stT[half][r][0];
        #pragma unroll
        for (int p = 0; p < TA / 2; p++) FFMA2(hacc[p], row[p], ww);
    }
    __syncthreads();
    #pragma unroll
    for (int p = 0; p < TA / 2; p++) {
        float2 x = upk2(hacc[p]);
        shT[half][f][2 * p]     = silu(x.x);
        shT[half][f][2 * p + 1] = silu(x.y);
    }
    __syncthreads();

    unsigned long long p0[TA / 2], p1[TA / 2], p2[TA / 2];
    {
        unsigned long long b0 = pk2(B2[f], B2[f]);
        unsigned long long b1 = pk2(B2[F + f], B2[F + f]);
        unsigned long long b2 = pk2(B2[2 * F + f], B2[2 * F + f]);
        #pragma unroll
        for (int p = 0; p < TA / 2; p++) { p0[p] = b0; p1[p] = b1; p2[p] = b2; }
    }
    for (int g = 0; g < F; g++) {
        const float* wr = W2 + g * F3;
        unsigned long long w0 = pk2(wr[f], wr[f]);
        unsigned long long w1 = pk2(wr[F + f], wr[F + f]);
        unsigned long long w2 = pk2(wr[2 * F + f], wr[2 * F + f]);
        const unsigned long long* row = (const unsigned long long*)&shT[half][g][0];
        #pragma unroll
        for (int p = 0; p < TA / 2; p++) {
            FFMA2(p0[p], row[p], w0);
            FFMA2(p1[p], row[p], w1);
            FFMA2(p2[p], row[p], w2);
        }
    }
    #pragma unroll
    for (int p = 0; p < TA / 2; p++) {
        float2 avv = upk2(p0[p]), asv = upk2(p1[p]), ass = upk2(p2[p]);
        #pragma unroll
        for (int h = 0; h < 2; h++) {
            int t = 2 * p + h;
            int a = a0 + t;
            float a_vv = h ? avv.y : avv.x;
            float a_sv = h ? asv.y : asv.x;
            float a_ss = h ? ass.y : ass.x;
            g_s[a * F + f] = snew[t] + uw[t] * a_sv + a_ss;
            #pragma unroll
            for (int d = 0; d < 3; d++)
                g_v[a * F3 + f * 3 + d] = svT[half][f][d][t] + u[t][d] * a_vv;
        }
    }
}

// ---------------------------------------------------------------------------
// readout: 16 atoms per block
// ---------------------------------------------------------------------------
#define TR 16

__global__ void k_zero_out(float* out)
{
    int t = threadIdx.x;
    if (t < NMOLS) out[t] = 0.0f;
}

__global__ void __launch_bounds__(128)
k_readout(const float* __restrict__ W1, const float* __restrict__ B1,
          const float* __restrict__ W2, const float* __restrict__ B2,
          const int* __restrict__ mol, float* __restrict__ out)
{
    int tid  = threadIdx.x;
    int half = tid >> 6;
    int t    = tid & 63;
    int ab   = blockIdx.x * TR;

    __shared__ float ssT[F][TR];
    __shared__ float red[TR][64];

    for (int x = tid; x < TR * F; x += 128) {
        int aa = x >> 7, ff = x & 127;
        ssT[ff][aa] = g_s[(ab + aa) * F + ff];
    }
    __syncthreads();

    unsigned long long acc[4];
    {
        unsigned long long b = pk2(B1[t], B1[t]);
        #pragma unroll
        for (int p = 0; p < 4; p++) acc[p] = b;
    }
    for (int g = 0; g < F; g++) {
        float w = W1[g * 64 + t];
        unsigned long long ww = pk2(w, w);
        const unsigned long long* row = (const unsigned long long*)&ssT[g][half * 8];
        #pragma unroll
        for (int p = 0; p < 4; p++) FFMA2(acc[p], row[p], ww);
    }
    float w2v = W2[t];
    #pragma unroll
    for (int p = 0; p < 4; p++) {
        float2 x = upk2(acc[p]);
        red[half * 8 + 2 * p][t]     = silu(x.x) * w2v;
        red[half * 8 + 2 * p + 1][t] = silu(x.y) * w2v;
    }
    __syncthreads();

    if (tid < TR) {
        float e = B2[0];
        #pragma unroll
        for (int q = 0; q < 64; q++) e += red[tid][q];
        atomicAdd(&out[mol[ab + tid]], e);
    }
}

// ---------------------------------------------------------------------------
// launch
// ---------------------------------------------------------------------------
extern "C" void kernel_launch(void* const* d_in, const int* in_sizes, int n_in,
                              void* d_out, int out_size)
{
    const float* xyz    = (const float*)d_in[0];
    const float* emb    = (const float*)d_in[1];
    const float* msg_w1 = (const float*)d_in[2];
    const float* msg_b1 = (const float*)d_in[3];
    const float* msg_w2 = (const float*)d_in[4];
    const float* msg_b2 = (const float*)d_in[5];
    const float* rbf_w  = (const float*)d_in[6];
    const float* rbf_b  = (const float*)d_in[7];
    const float* upd_u  = (const float*)d_in[8];
    const float* upd_v  = (const float*)d_in[9];
    const float* upd_w1 = (const float*)d_in[10];
    const float* upd_b1 = (const float*)d_in[11];
    const float* upd_w2 = (const float*)d_in[12];
    const float* upd_b2 = (const float*)d_in[13];
    const float* ro_w1  = (const float*)d_in[14];
    const float* ro_b1  = (const float*)d_in[15];
    const float* ro_w2  = (const float*)d_in[16];
    const float* ro_b2  = (const float*)d_in[17];
    const int*   z      = (const int*)d_in[18];
    const int*   nbrs   = (const int*)d_in[19];
    const int*   mol    = (const int*)d_in[20];
    float*       out    = (float*)d_out;

    int E = in_sizes[19] / 2;

    k_init <<<NATOMS, 128>>>(emb, z);
    k_edges<<<(E + 255) / 256, 256>>>(xyz, nbrs, E);

    for (int c = 0; c < NCONV; c++) {
        k_ws <<<NEDGES / EW, 128>>>(rbf_w + c * NRBF * F3, rbf_b + c * F3);
        k_phi<<<NATOMS / (2 * TA), 256>>>(msg_w1 + c * F * F,     msg_b1 + c * F,
                                          msg_w2 + c * F * F3,    msg_b2 + c * F3);
        k_msg<<<NATOMS / TAM, 128>>>();
        k_upd<<<NATOMS / (2 * TA), 256>>>(upd_u  + c * F * F,     upd_v  + c * F * F,
                                          upd_w1 + c * 2 * F * F, upd_b1 + c * F,
                                          upd_w2 + c * F * F3,    upd_b2 + c * F3);
    }

    k_zero_out<<<1, 128>>>(out);
    k_readout <<<NATOMS / TR, 128>>>(ro_w1, ro_b1, ro_w2, ro_b2, mol, out);
}

// round 7
// speedup vs baseline: 1.4999x; 1.1274x over previous
#include <cuda_runtime.h>
#include <math.h>

// ---- problem constants ----
#define F      128
#define F3     384
#define NRBF   20
#define NATOMS 8000
#define NEDGES 160000
#define NMOLS  100
#define NCONV  3
#define CUTOFF 5.0f

#define TA  8    // atoms per half in phi/upd kernels (16 per block)
#define TAM 4    // atoms per block in msg kernel
#define CAP 64   // max active edges per destination atom

// ---- device scratch ----
__device__ float g_s   [NATOMS * F];
__device__ float g_v   [NATOMS * F3];
__device__ float g_ds  [NATOMS * F];
__device__ float g_dv  [NATOMS * F3];
__device__ float g_phi [NATOMS * F3];
__device__ float g_rbf [NEDGES * NRBF];   // env-premultiplied
__device__ float g_env [NEDGES];
__device__ float g_unit[NEDGES * 3];
__device__ int   g_cnt [NATOMS];
__device__ int   g_list[NATOMS * CAP];

__device__ __forceinline__ float silu(float x) { return x / (1.0f + __expf(-x)); }

// packed fp32x2 helpers
#define FFMA2(acc, a, b) asm("fma.rn.f32x2 %0, %1, %2, %0;" : "+l"(acc) : "l"(a), "l"(b))
#define ADDX2(out, a, b) asm("add.rn.f32x2 %0, %1, %2;" : "=l"(out) : "l"(a), "l"(b))
__device__ __forceinline__ unsigned long long pk2(float x, float y) {
    unsigned long long r; asm("mov.b64 %0, {%1, %2};" : "=l"(r) : "f"(x), "f"(y)); return r;
}
__device__ __forceinline__ float2 upk2(unsigned long long v) {
    float2 o; asm("mov.b64 {%0, %1}, %2;" : "=f"(o.x), "=f"(o.y) : "l"(v)); return o;
}

// ---------------------------------------------------------------------------
// init
// ---------------------------------------------------------------------------
__global__ void k_init(const float* __restrict__ emb, const int* __restrict__ z)
{
    int a = blockIdx.x, f = threadIdx.x;
    g_s[a * F + f] = emb[z[a] * F + f];
    int b = a * F3 + f * 3;
    g_v[b] = 0.0f; g_v[b + 1] = 0.0f; g_v[b + 2] = 0.0f;
    if (f == 0) g_cnt[a] = 0;
}

// ---------------------------------------------------------------------------
// edge geometry + CSR build
// ---------------------------------------------------------------------------
__global__ void k_edges(const float* __restrict__ xyz, const int* __restrict__ nbrs, int E)
{
    int e = blockIdx.x * 256 + threadIdx.x;
    if (e >= E) return;
    int i = nbrs[2 * e], j = nbrs[2 * e + 1];
    float rx = xyz[3 * j]     - xyz[3 * i];
    float ry = xyz[3 * j + 1] - xyz[3 * i + 1];
    float rz = xyz[3 * j + 2] - xyz[3 * i + 2];
    float d  = sqrtf(rx * rx + ry * ry + rz * rz);
    float inv = 1.0f / d;
    float t = d * (1.0f / CUTOFF);
    if (d <= CUTOFF) {
        float env = 0.5f * (cospif(t) + 1.0f);
        g_env[e] = env;
        g_unit[3 * e]     = rx * inv;
        g_unit[3 * e + 1] = ry * inv;
        g_unit[3 * e + 2] = rz * inv;
        float s = env * inv;
        #pragma unroll
        for (int k = 0; k < NRBF; k++)
            g_rbf[e * NRBF + k] = sinpif((float)(k + 1) * t) * s;
        int pos = atomicAdd(&g_cnt[i], 1);
        if (pos < CAP) g_list[i * CAP + pos] = e;
    }
}

// ---------------------------------------------------------------------------
// phi = silu(s @ W1 + b1) @ W2 + b2   (256 threads = 2 halves, 16 atoms/block)
// ---------------------------------------------------------------------------
__global__ void __launch_bounds__(256)
k_phi(const float* __restrict__ W1, const float* __restrict__ B1,
      const float* __restrict__ W2, const float* __restrict__ B2)
{
    int tid  = threadIdx.x;
    int half = tid >> 7;
    int f    = tid & 127;
    int a0   = blockIdx.x * (2 * TA) + half * TA;

    __shared__ float ssT[2][F][TA];
    __shared__ float hhT[2][F][TA];

    #pragma unroll
    for (int t = 0; t < TA; t++) ssT[half][f][t] = g_s[(a0 + t) * F + f];
    __syncthreads();

    unsigned long long acc[TA / 2];
    {
        unsigned long long b = pk2(B1[f], B1[f]);
        #pragma unroll
        for (int p = 0; p < TA / 2; p++) acc[p] = b;
    }
    for (int g = 0; g < F; g++) {
        float w = W1[g * F + f];
        unsigned long long ww = pk2(w, w);
        const unsigned long long* row = (const unsigned long long*)&ssT[half][g][0];
        #pragma unroll
        for (int p = 0; p < TA / 2; p++) FFMA2(acc[p], row[p], ww);
    }
    #pragma unroll
    for (int p = 0; p < TA / 2; p++) {
        float2 x = upk2(acc[p]);
        hhT[half][f][2 * p]     = silu(x.x);
        hhT[half][f][2 * p + 1] = silu(x.y);
    }
    __syncthreads();

    unsigned long long p0[TA / 2], p1[TA / 2], p2[TA / 2];
    {
        unsigned long long b0 = pk2(B2[f], B2[f]);
        unsigned long long b1 = pk2(B2[F + f], B2[F + f]);
        unsigned long long b2 = pk2(B2[2 * F + f], B2[2 * F + f]);
        #pragma unroll
        for (int p = 0; p < TA / 2; p++) { p0[p] = b0; p1[p] = b1; p2[p] = b2; }
    }
    for (int g = 0; g < F; g++) {
        const float* w = W2 + g * F3;
        unsigned long long w0 = pk2(w[f], w[f]);
        unsigned long long w1 = pk2(w[F + f], w[F + f]);
        unsigned long long w2 = pk2(w[2 * F + f], w[2 * F + f]);
        const unsigned long long* row = (const unsigned long long*)&hhT[half][g][0];
        #pragma unroll
        for (int p = 0; p < TA / 2; p++) {
            FFMA2(p0[p], row[p], w0);
            FFMA2(p1[p], row[p], w1);
            FFMA2(p2[p], row[p], w2);
        }
    }
    #pragma unroll
    for (int p = 0; p < TA / 2; p++) {
        float2 x0 = upk2(p0[p]), x1 = upk2(p1[p]), x2 = upk2(p2[p]);
        int a = a0 + 2 * p;
        g_phi[a * F3 + f]               = x0.x;
        g_phi[(a + 1) * F3 + f]         = x0.y;
        g_phi[a * F3 + F + f]           = x1.x;
        g_phi[(a + 1) * F3 + F + f]     = x1.y;
        g_phi[a * F3 + 2 * F + f]       = x2.x;
        g_phi[(a + 1) * F3 + 2 * F + f] = x2.y;
    }
}

// ---------------------------------------------------------------------------
// message pass over CSR buckets (R4 structure + depth-2 prefetch).
// ch0/ch1 rbf weights in regs as packed pairs; ch2 weights in smem.
// 4 accumulation chains; phi[j]/v[j] gathers prefetched TWO edges ahead
// in two register buffers (loop unrolled by 2).
// ---------------------------------------------------------------------------
__global__ void __launch_bounds__(128)
k_msg(const float* __restrict__ RW, const float* __restrict__ RB,
      const int* __restrict__ nbrs)
{
    __shared__ float rw2s[NRBF * F];   // ch2 weights, 10 KB
    __shared__ int   sj  [CAP];
    __shared__ float senv[CAP];
    __shared__ float sux [CAP];
    __shared__ float suy [CAP];
    __shared__ float suz [CAP];
    __shared__ float srbf[CAP][NRBF];

    int f = threadIdx.x;

    unsigned long long rw01[NRBF];
    #pragma unroll
    for (int q = 0; q < NRBF; q++)
        rw01[q] = pk2(RW[q * F3 + f], RW[q * F3 + F + f]);
    for (int idx = f; idx < NRBF * F; idx += 128) {
        int q = idx >> 7, ff = idx & 127;
        rw2s[idx] = RW[q * F3 + 2 * F + ff];
    }
    float rb0 = RB[f], rb1 = RB[F + f], rb2 = RB[2 * F + f];

    int abase = blockIdx.x * TAM;

    for (int it = 0; it < TAM; it++) {
        int a = abase + it;
        int n = g_cnt[a];
        if (n > CAP) n = CAP;

        __syncthreads();   // prev iter smem reads done; also covers rw2s fill
        if (f < n) {
            int e = g_list[a * CAP + f];
            sj  [f] = nbrs[2 * e + 1];
            senv[f] = g_env[e];
            sux [f] = g_unit[3 * e];
            suy [f] = g_unit[3 * e + 1];
            suz [f] = g_unit[3 * e + 2];
            const float4* rp = (const float4*)(g_rbf + e * NRBF);
            float4* dst = (float4*)&srbf[f][0];
            #pragma unroll
            for (int x = 0; x < NRBF / 4; x++) dst[x] = rp[x];
        }
        __syncthreads();

        float ds = 0.0f, dv0 = 0.0f, dv1 = 0.0f, dv2 = 0.0f;

        // two prefetch buffers: A holds even-indexed edge data, B odd
        float pa0 = 0.f, pa1 = 0.f, pa2 = 0.f, va0 = 0.f, va1 = 0.f, va2 = 0.f;
        float pb0 = 0.f, pb1 = 0.f, pb2 = 0.f, vb0 = 0.f, vb1 = 0.f, vb2 = 0.f;

        #define MSG_LD(m, P0, P1, P2, V0, V1, V2)                     \
            do {                                                      \
                int _j = sj[m];                                       \
                const float* _pj = g_phi + _j * F3;                   \
                P0 = _pj[f]; P1 = _pj[F + f]; P2 = _pj[2 * F + f];    \
                const float* _vj = g_v + _j * F3 + f * 3;             \
                V0 = _vj[0]; V1 = _vj[1]; V2 = _vj[2];                \
            } while (0)

        #define MSG_ACC(m, P0, P1, P2, V0, V1, V2)                    \
            do {                                                      \
                float _env = senv[m];                                 \
                unsigned long long _wA = pk2(_env * rb0, _env * rb1); \
                unsigned long long _wB = pk2(0.0f, 0.0f);             \
                float _w2a = _env * rb2, _w2b = 0.0f;                 \
                _Pragma("unroll")                                     \
                for (int q = 0; q < NRBF; q += 2) {                   \
                    float _r0 = srbf[m][q];                           \
                    float _r1 = srbf[m][q + 1];                       \
                    FFMA2(_wA, pk2(_r0, _r0), rw01[q]);               \
                    FFMA2(_wB, pk2(_r1, _r1), rw01[q + 1]);           \
                    _w2a = fmaf(_r0, rw2s[q * F + f], _w2a);          \
                    _w2b = fmaf(_r1, rw2s[(q + 1) * F + f], _w2b);    \
                }                                                     \
                float2 _xa = upk2(_wA), _xb = upk2(_wB);              \
                float _w0 = _xa.x + _xb.x;                            \
                float _w1 = _xa.y + _xb.y;                            \
                float _w2 = _w2a + _w2b;                              \
                float _sp0 = P0 * _w0;                                \
                float _sp1 = P1 * _w1;                                \
                float _sp2 = P2 * _w2;                                \
                ds  += _sp1;                                          \
                dv0 += _sp2 * sux[m] + _sp0 * V0;                     \
                dv1 += _sp2 * suy[m] + _sp0 * V1;                     \
                dv2 += _sp2 * suz[m] + _sp0 * V2;                     \
            } while (0)

        if (n > 0) MSG_LD(0, pa0, pa1, pa2, va0, va1, va2);
        if (n > 1) MSG_LD(1, pb0, pb1, pb2, vb0, vb1, vb2);

        for (int k = 0; k < n; k += 2) {
            // edge k (buffer A): copy to locals, refill A with edge k+2
            {
                float c0 = pa0, c1 = pa1, c2 = pa2;
                float d0 = va0, d1 = va1, d2 = va2;
                if (k + 2 < n) MSG_LD(k + 2, pa0, pa1, pa2, va0, va1, va2);
                MSG_ACC(k, c0, c1, c2, d0, d1, d2);
            }
            // edge k+1 (buffer B): copy to locals, refill B with edge k+3
            if (k + 1 < n) {
                float c0 = pb0, c1 = pb1, c2 = pb2;
                float d0 = vb0, d1 = vb1, d2 = vb2;
                if (k + 3 < n) MSG_LD(k + 3, pb0, pb1, pb2, vb0, vb1, vb2);
                MSG_ACC(k + 1, c0, c1, c2, d0, d1, d2);
            }
        }
        #undef MSG_LD
        #undef MSG_ACC

        g_ds[a * F + f] = ds;
        g_dv[a * F3 + f * 3]     = dv0;
        g_dv[a * F3 + f * 3 + 1] = dv1;
        g_dv[a * F3 + f * 3 + 2] = dv2;
    }
}

// ---------------------------------------------------------------------------
// update block (256 threads = 2 halves x 8 atoms)
// ---------------------------------------------------------------------------
__global__ void __launch_bounds__(256)
k_upd(const float* __restrict__ U,  const float* __restrict__ V,
      const float* __restrict__ W1, const float* __restrict__ B1,
      const float* __restrict__ W2, const float* __restrict__ B2)
{
    int tid  = threadIdx.x;
    int half = tid >> 7;
    int f    = tid & 127;
    int a0   = blockIdx.x * (2 * TA) + half * TA;

    __shared__ float svT[2][F][3][TA];    // 24 KB
    __shared__ float stT[2][2 * F][TA];   // 16 KB (reused as shT after W1 pass)
    float (*shT)[F][TA] = (float (*)[F][TA])&stT[0][0][0];

    float snew[TA];
    #pragma unroll
    for (int t = 0; t < TA; t++) {
        int a = a0 + t;
        float s1 = g_s[a * F + f] + g_ds[a * F + f];
        snew[t]         = s1;
        stT[half][f][t] = s1;
        #pragma unroll
        for (int d = 0; d < 3; d++)
            svT[half][f][d][t] = g_v[a * F3 + f * 3 + d] + g_dv[a * F3 + f * 3 + d];
    }
    __syncthreads();

    unsigned long long ua[3][TA / 2], wa[3][TA / 2];
    #pragma unroll
    for (int d = 0; d < 3; d++)
        #pragma unroll
        for (int p = 0; p < TA / 2; p++) { ua[d][p] = 0ULL; wa[d][p] = 0ULL; }
    for (int g = 0; g < F; g++) {
        float Ug = U[g * F + f], Vg = V[g * F + f];
        unsigned long long Up = pk2(Ug, Ug), Vp = pk2(Vg, Vg);
        #pragma unroll
        for (int d = 0; d < 3; d++) {
            const unsigned long long* row = (const unsigned long long*)&svT[half][g][d][0];
            #pragma unroll
            for (int p = 0; p < TA / 2; p++) {
                unsigned long long r = row[p];
                FFMA2(ua[d][p], r, Up);
                FFMA2(wa[d][p], r, Vp);
            }
        }
    }
    float u[TA][3], uw[TA];
    #pragma unroll
    for (int p = 0; p < TA / 2; p++) {
        float wv[2][3];
        #pragma unroll
        for (int d = 0; d < 3; d++) {
            float2 xu = upk2(ua[d][p]);
            float2 xw = upk2(wa[d][p]);
            u[2 * p][d] = xu.x; u[2 * p + 1][d] = xu.y;
            wv[0][d] = xw.x;    wv[1][d] = xw.y;
        }
        #pragma unroll
        for (int h = 0; h < 2; h++) {
            int t = 2 * p + h;
            float n2 = wv[h][0] * wv[h][0] + wv[h][1] * wv[h][1] + wv[h][2] * wv[h][2];
            stT[half][F + f][t] = sqrtf(n2 + 1e-15f);
            uw[t] = u[t][0] * wv[h][0] + u[t][1] * wv[h][1] + u[t][2] * wv[h][2];
        }
    }
    __syncthreads();

    unsigned long long hacc[TA / 2];
    {
        unsigned long long b = pk2(B1[f], B1[f]);
        #pragma unroll
        for (int p = 0; p < TA / 2; p++) hacc[p] = b;
    }
    for (int r = 0; r < 2 * F; r++) {
        float wv = W1[r * F + f];
        unsigned long long ww = pk2(wv, wv);
        const unsigned long long* row = (const unsigned long long*)&stT[half][r][0];
        #pragma unroll
        for (int p = 0; p < TA / 2; p++) FFMA2(hacc[p], row[p], ww);
    }
    __syncthreads();
    #pragma unroll
    for (int p = 0; p < TA / 2; p++) {
        float2 x = upk2(hacc[p]);
        shT[half][f][2 * p]     = silu(x.x);
        shT[half][f][2 * p + 1] = silu(x.y);
    }
    __syncthreads();

    unsigned long long p0[TA / 2], p1[TA / 2], p2[TA / 2];
    {
        unsigned long long b0 = pk2(B2[f], B2[f]);
        unsigned long long b1 = pk2(B2[F + f], B2[F + f]);
        unsigned long long b2 = pk2(B2[2 * F + f], B2[2 * F + f]);
        #pragma unroll
        for (int p = 0; p < TA / 2; p++) { p0[p] = b0; p1[p] = b1; p2[p] = b2; }
    }
    for (int g = 0; g < F; g++) {
        const float* wr = W2 + g * F3;
        unsigned long long w0 = pk2(wr[f], wr[f]);
        unsigned long long w1 = pk2(wr[F + f], wr[F + f]);
        unsigned long long w2 = pk2(wr[2 * F + f], wr[2 * F + f]);
        const unsigned long long* row = (const unsigned long long*)&shT[half][g][0];
        #pragma unroll
        for (int p = 0; p < TA / 2; p++) {
            FFMA2(p0[p], row[p], w0);
            FFMA2(p1[p], row[p], w1);
            FFMA2(p2[p], row[p], w2);
        }
    }
    #pragma unroll
    for (int p = 0; p < TA / 2; p++) {
        float2 avv = upk2(p0[p]), asv = upk2(p1[p]), ass = upk2(p2[p]);
        #pragma unroll
        for (int h = 0; h < 2; h++) {
            int t = 2 * p + h;
            int a = a0 + t;
            float a_vv = h ? avv.y : avv.x;
            float a_sv = h ? asv.y : asv.x;
            float a_ss = h ? ass.y : ass.x;
            g_s[a * F + f] = snew[t] + uw[t] * a_sv + a_ss;
            #pragma unroll
            for (int d = 0; d < 3; d++)
                g_v[a * F3 + f * 3 + d] = svT[half][f][d][t] + u[t][d] * a_vv;
        }
    }
}

// ---------------------------------------------------------------------------
// readout: 16 atoms per block
// ---------------------------------------------------------------------------
#define TR 16

__global__ void k_zero_out(float* out)
{
    int t = threadIdx.x;
    if (t < NMOLS) out[t] = 0.0f;
}

__global__ void __launch_bounds__(128)
k_readout(const float* __restrict__ W1, const float* __restrict__ B1,
          const float* __restrict__ W2, const float* __restrict__ B2,
          const int* __restrict__ mol, float* __restrict__ out)
{
    int tid  = threadIdx.x;
    int half = tid >> 6;
    int t    = tid & 63;
    int ab   = blockIdx.x * TR;

    __shared__ float ssT[F][TR];
    __shared__ float red[TR][64];

    for (int x = tid; x < TR * F; x += 128) {
        int aa = x >> 7, ff = x & 127;
        ssT[ff][aa] = g_s[(ab + aa) * F + ff];
    }
    __syncthreads();

    unsigned long long acc[4];
    {
        unsigned long long b = pk2(B1[t], B1[t]);
        #pragma unroll
        for (int p = 0; p < 4; p++) acc[p] = b;
    }
    for (int g = 0; g < F; g++) {
        float w = W1[g * 64 + t];
        unsigned long long ww = pk2(w, w);
        const unsigned long long* row = (const unsigned long long*)&ssT[g][half * 8];
        #pragma unroll
        for (int p = 0; p < 4; p++) FFMA2(acc[p], row[p], ww);
    }
    float w2v = W2[t];
    #pragma unroll
    for (int p = 0; p < 4; p++) {
        float2 x = upk2(acc[p]);
        red[half * 8 + 2 * p][t]     = silu(x.x) * w2v;
        red[half * 8 + 2 * p + 1][t] = silu(x.y) * w2v;
    }
    __syncthreads();

    if (tid < TR) {
        float e = B2[0];
        #pragma unroll
        for (int q = 0; q < 64; q++) e += red[tid][q];
        atomicAdd(&out[mol[ab + tid]], e);
    }
}

// ---------------------------------------------------------------------------
// launch
// ---------------------------------------------------------------------------
extern "C" void kernel_launch(void* const* d_in, const int* in_sizes, int n_in,
                              void* d_out, int out_size)
{
    const float* xyz    = (const float*)d_in[0];
    const float* emb    = (const float*)d_in[1];
    const float* msg_w1 = (const float*)d_in[2];
    const float* msg_b1 = (const float*)d_in[3];
    const float* msg_w2 = (const float*)d_in[4];
    const float* msg_b2 = (const float*)d_in[5];
    const float* rbf_w  = (const float*)d_in[6];
    const float* rbf_b  = (const float*)d_in[7];
    const float* upd_u  = (const float*)d_in[8];
    const float* upd_v  = (const float*)d_in[9];
    const float* upd_w1 = (const float*)d_in[10];
    const float* upd_b1 = (const float*)d_in[11];
    const float* upd_w2 = (const float*)d_in[12];
    const float* upd_b2 = (const float*)d_in[13];
    const float* ro_w1  = (const float*)d_in[14];
    const float* ro_b1  = (const float*)d_in[15];
    const float* ro_w2  = (const float*)d_in[16];
    const float* ro_b2  = (const float*)d_in[17];
    const int*   z      = (const int*)d_in[18];
    const int*   nbrs   = (const int*)d_in[19];
    const int*   mol    = (const int*)d_in[20];
    float*       out    = (float*)d_out;

    int E = in_sizes[19] / 2;

    k_init <<<NATOMS, 128>>>(emb, z);
    k_edges<<<(E + 255) / 256, 256>>>(xyz, nbrs, E);

    for (int c = 0; c < NCONV; c++) {
        k_phi<<<NATOMS / (2 * TA), 256>>>(msg_w1 + c * F * F,     msg_b1 + c * F,
                                          msg_w2 + c * F * F3,    msg_b2 + c * F3);
        k_msg<<<NATOMS / TAM, 128>>>(rbf_w + c * NRBF * F3, rbf_b + c * F3, nbrs);
        k_upd<<<NATOMS / (2 * TA), 256>>>(upd_u  + c * F * F,     upd_v  + c * F * F,
                                          upd_w1 + c * 2 * F * F, upd_b1 + c * F,
                                          upd_w2 + c * F * F3,    upd_b2 + c * F3);
    }

    k_zero_out<<<1, 128>>>(out);
    k_readout <<<NATOMS / TR, 128>>>(ro_w1, ro_b1, ro_w2, ro_b2, mol, out);
}